// round 3
// baseline (speedup 1.0000x reference)
#include <cuda_runtime.h>

#define N_BINS 15
#define C 128

// Global scratch (allocation-free rule): per-bin accumulators.
__device__ double             g_conf_sum[N_BINS];
__device__ unsigned long long g_cnt[N_BINS];
__device__ unsigned long long g_acc[N_BINS];

__global__ void ece_init_kernel() {
    int i = threadIdx.x;
    if (i < N_BINS) {
        g_conf_sum[i] = 0.0;
        g_cnt[i] = 0ull;
        g_acc[i] = 0ull;
    }
}

// One warp per row: lane j loads float4 -> 512B coalesced per row.
__global__ void ece_main_kernel(const float* __restrict__ logits,
                                const int* __restrict__ labels,
                                int N) {
    __shared__ double       s_conf[N_BINS];
    __shared__ unsigned int s_cnt[N_BINS];
    __shared__ unsigned int s_acc[N_BINS];

    int tid = threadIdx.x;
    if (tid < N_BINS) {
        s_conf[tid] = 0.0;
        s_cnt[tid] = 0u;
        s_acc[tid] = 0u;
    }
    __syncthreads();

    const int lane = tid & 31;
    const int warp = tid >> 5;
    const int warps_per_block = blockDim.x >> 5;
    long long row0   = (long long)blockIdx.x * warps_per_block + warp;
    long long stride = (long long)gridDim.x * warps_per_block;

    for (long long row = row0; row < N; row += stride) {
        const float4 v =
            reinterpret_cast<const float4*>(logits + row * C)[lane];

        // lane-local max + argmax (first occurrence)
        float m = v.x;
        int mi = lane * 4;
        if (v.y > m) { m = v.y; mi = lane * 4 + 1; }
        if (v.z > m) { m = v.z; mi = lane * 4 + 2; }
        if (v.w > m) { m = v.w; mi = lane * 4 + 3; }

        // butterfly argmax: all lanes end with row max + its index
        #pragma unroll
        for (int o = 16; o; o >>= 1) {
            float om = __shfl_xor_sync(0xffffffffu, m, o);
            int   oi = __shfl_xor_sync(0xffffffffu, mi, o);
            if (om > m || (om == m && oi < mi)) { m = om; mi = oi; }
        }

        // sum of exp(l - max); max term contributes exactly 1
        float s = __expf(v.x - m) + __expf(v.y - m) +
                  __expf(v.z - m) + __expf(v.w - m);
        #pragma unroll
        for (int o = 16; o; o >>= 1)
            s += __shfl_xor_sync(0xffffffffu, s, o);

        if (lane == 0) {
            float conf = 1.0f / s;                       // = max softmax prob
            int b = (int)ceilf(conf * (float)N_BINS) - 1;
            b = min(max(b, 0), N_BINS - 1);
            atomicAdd(&s_conf[b], (double)conf);
            atomicAdd(&s_cnt[b], 1u);
            if (mi == labels[row]) atomicAdd(&s_acc[b], 1u);
        }
    }

    __syncthreads();
    if (tid < N_BINS && s_cnt[tid] != 0u) {
        atomicAdd(&g_conf_sum[tid], s_conf[tid]);
        atomicAdd(&g_cnt[tid], (unsigned long long)s_cnt[tid]);
        atomicAdd(&g_acc[tid], (unsigned long long)s_acc[tid]);
    }
}

__global__ void ece_final_kernel(float* __restrict__ out, int N) {
    if (threadIdx.x == 0) {
        double ece = 0.0;
        double n = (double)N;
        #pragma unroll
        for (int i = 0; i < N_BINS; i++) {
            double c = (double)g_cnt[i];
            if (c > 0.0) {
                double diff = fabs(g_conf_sum[i] / c - (double)g_acc[i] / c);
                ece += diff * (c / n);
            }
        }
        out[0] = (float)ece;
    }
}

extern "C" void kernel_launch(void* const* d_in, const int* in_sizes, int n_in,
                              void* d_out, int out_size) {
    const float* logits = (const float*)d_in[0];
    const int*   labels = (const int*)d_in[1];
    int N = in_sizes[1];  // labels element count = number of rows

    ece_init_kernel<<<1, 32>>>();

    // Persistent-ish grid: 1184 blocks x 8 warps = 9472 warps, ~111 rows/warp.
    ece_main_kernel<<<1184, 256>>>(logits, labels, N);

    ece_final_kernel<<<1, 32>>>((float*)d_out, N);
}

// round 5
// speedup vs baseline: 1.4548x; 1.4548x over previous
#include <cuda_runtime.h>

#define N_BINS 15
#define C 128
#define ROWS_PER_ITER 4
#define WARPS_PER_BLOCK 8

// Global scratch (allocation-free rule): per-bin accumulators.
__device__ double             g_conf_sum[N_BINS];
__device__ unsigned long long g_cnt[N_BINS];
__device__ unsigned long long g_acc[N_BINS];

__global__ void ece_init_kernel() {
    int i = threadIdx.x;
    if (i < N_BINS) {
        g_conf_sum[i] = 0.0;
        g_cnt[i] = 0ull;
        g_acc[i] = 0ull;
    }
}

// One warp per row-group of 4: 4 independent float4 loads per lane per iter
// (MLP=4), value-only max butterfly + ballot argmax, per-warp private bins.
__global__ void __launch_bounds__(WARPS_PER_BLOCK * 32)
ece_main_kernel(const float* __restrict__ logits,
                const int* __restrict__ labels,
                int N) {
    __shared__ double       s_conf[WARPS_PER_BLOCK][N_BINS];
    __shared__ unsigned int s_cnt[WARPS_PER_BLOCK][N_BINS];
    __shared__ unsigned int s_acc[WARPS_PER_BLOCK][N_BINS];

    const int tid  = threadIdx.x;
    const int lane = tid & 31;
    const int warp = tid >> 5;

    if (lane < N_BINS) {
        s_conf[warp][lane] = 0.0;
        s_cnt[warp][lane]  = 0u;
        s_acc[warp][lane]  = 0u;
    }
    __syncthreads();

    const long long gwarp       = (long long)blockIdx.x * WARPS_PER_BLOCK + warp;
    const long long total_warps = (long long)gridDim.x * WARPS_PER_BLOCK;

    // N is a multiple of 4; each group of 4 rows is fully valid if base < N.
    for (long long base = gwarp * ROWS_PER_ITER; base < N;
         base += total_warps * ROWS_PER_ITER) {

        // Front-batched independent loads: 4 x LDG.128 per lane.
        float4 v[ROWS_PER_ITER];
        #pragma unroll
        for (int r = 0; r < ROWS_PER_ITER; r++)
            v[r] = reinterpret_cast<const float4*>(
                       logits + (base + r) * C)[lane];

        int4 lab4;
        if (lane == 0)
            lab4 = *reinterpret_cast<const int4*>(labels + base);

        #pragma unroll
        for (int r = 0; r < ROWS_PER_ITER; r++) {
            const float4 x = v[r];

            // value-only row max (5 shuffles)
            float m = fmaxf(fmaxf(x.x, x.y), fmaxf(x.z, x.w));
            #pragma unroll
            for (int o = 16; o; o >>= 1)
                m = fmaxf(m, __shfl_xor_sync(0xffffffffu, m, o));

            // exp-sum (max term contributes exactly 1)
            float s = __expf(x.x - m) + __expf(x.y - m) +
                      __expf(x.z - m) + __expf(x.w - m);
            #pragma unroll
            for (int o = 16; o; o >>= 1)
                s += __shfl_xor_sync(0xffffffffu, s, o);

            // first-occurrence argmax: lowest local idx equal to m, then
            // lowest lane holding the max wins (ballot + 1 shfl).
            int cand = 0x7fffffff;
            if (x.w == m) cand = lane * 4 + 3;
            if (x.z == m) cand = lane * 4 + 2;
            if (x.y == m) cand = lane * 4 + 1;
            if (x.x == m) cand = lane * 4;
            unsigned bal = __ballot_sync(0xffffffffu, cand != 0x7fffffff);
            int pred = __shfl_sync(0xffffffffu, cand, __ffs(bal) - 1);

            if (lane == 0) {
                float conf = 1.0f / s;
                int b = (int)ceilf(conf * (float)N_BINS) - 1;
                b = min(max(b, 0), N_BINS - 1);
                int lab = (r == 0) ? lab4.x : (r == 1) ? lab4.y
                          : (r == 2) ? lab4.z : lab4.w;
                // per-warp private bins: plain RMW, no atomics
                s_conf[warp][b] += (double)conf;
                s_cnt[warp][b]  += 1u;
                s_acc[warp][b]  += (pred == lab) ? 1u : 0u;
            }
        }
    }

    __syncthreads();
    if (tid < N_BINS) {
        double       csum = 0.0;
        unsigned int cnt = 0u, acc = 0u;
        #pragma unroll
        for (int w = 0; w < WARPS_PER_BLOCK; w++) {
            csum += s_conf[w][tid];
            cnt  += s_cnt[w][tid];
            acc  += s_acc[w][tid];
        }
        if (cnt != 0u) {
            atomicAdd(&g_conf_sum[tid], csum);
            atomicAdd(&g_cnt[tid], (unsigned long long)cnt);
            atomicAdd(&g_acc[tid], (unsigned long long)acc);
        }
    }
}

__global__ void ece_final_kernel(float* __restrict__ out, int N) {
    if (threadIdx.x == 0) {
        double ece = 0.0;
        double n = (double)N;
        #pragma unroll
        for (int i = 0; i < N_BINS; i++) {
            double c = (double)g_cnt[i];
            if (c > 0.0) {
                double diff = fabs(g_conf_sum[i] / c - (double)g_acc[i] / c);
                ece += diff * (c / n);
            }
        }
        out[0] = (float)ece;
    }
}

extern "C" void kernel_launch(void* const* d_in, const int* in_sizes, int n_in,
                              void* d_out, int out_size) {
    const float* logits = (const float*)d_in[0];
    const int*   labels = (const int*)d_in[1];
    int N = in_sizes[1];  // labels element count = number of rows

    ece_init_kernel<<<1, 32>>>();
    ece_main_kernel<<<1184, WARPS_PER_BLOCK * 32>>>(logits, labels, N);
    ece_final_kernel<<<1, 32>>>((float*)d_out, N);
}